// round 4
// baseline (speedup 1.0000x reference)
#include <cuda_runtime.h>
#include <cstdint>

#define TOK   16384
#define DIM   2048
#define NE    16
#define BT    128
#define NTHR  256
#define NCHUNK (DIM / 64)        // 32 chunks of 64 dims

// stage = x[128 tok][64 f] (32768 B) + W[16 e][64 f] (4096 B)
#define XSTAGE_B  32768u
#define STAGE_B   36864u
#define MBAR_OFF  110592u        // 3 stages end
#define LS_OFF    110720u        // logits [128][17] floats
#define SMEM_BYTES (110720 + 128*17*4)   // 119424

__device__ __forceinline__ uint32_t smem_u32(const void* p) {
    uint32_t a;
    asm("{ .reg .u64 t; cvta.to.shared.u64 t, %1; cvt.u32.u64 %0, t; }" : "=r"(a) : "l"(p));
    return a;
}

#define MBARRIER_INIT(addr, cnt) \
    asm volatile("mbarrier.init.shared.b64 [%0], %1;" :: "r"(addr), "r"(cnt) : "memory")
#define MBARRIER_EXPECT_TX(addr, bytes) \
    asm volatile("mbarrier.arrive.expect_tx.shared.b64 _, [%0], %1;" :: "r"(addr), "r"(bytes) : "memory")
#define MBARRIER_WAIT_PARITY(addr, par) do {                                   \
    uint32_t _m = (addr); uint32_t _p = (par); uint32_t _d;                    \
    asm volatile("{\n\t.reg .pred p;\n\t"                                      \
        "mbarrier.try_wait.parity.acquire.cta.shared::cta.b64 p, [%1], %2;\n\t"\
        "selp.b32 %0, 1, 0, p;\n\t}"                                           \
        : "=r"(_d) : "r"(_m), "r"(_p) : "memory");                             \
    if (!_d) {                                                                 \
        asm volatile("{\n\t.reg .pred P1;\n\t"                                 \
            "WL_%=:\n\t"                                                       \
            "mbarrier.try_wait.parity.acquire.cta.shared::cta.b64 P1, [%0], %1, 0x989680;\n\t" \
            "@P1 bra.uni WD_%=;\n\t"                                           \
            "bra.uni WL_%=;\n\t"                                               \
            "WD_%=:\n\t}" :: "r"(_m), "r"(_p) : "memory");                     \
    }                                                                          \
} while (0)

#define BULK_CP256(dst, gsrc, mbar) \
    asm volatile("cp.async.bulk.shared::cluster.global.mbarrier::complete_tx::bytes [%0], [%1], %2, [%3];" \
        :: "r"(dst), "l"(gsrc), "r"(256u), "r"(mbar) : "memory")

#define FMA2(c, a, b) asm("fma.rn.f32x2 %0, %1, %2, %0;" : "+l"(c) : "l"(a), "l"(b))
#define LDSV2(a, b, addr) \
    asm volatile("ld.shared.v2.b64 {%0, %1}, [%2];" : "=l"(a), "=l"(b) : "r"(addr))
#define STS32(addr, v) asm volatile("st.shared.f32 [%0], %1;" :: "r"(addr), "f"(v))
#define LDS32(v, addr) asm volatile("ld.shared.f32 %0, [%1];" : "=f"(v) : "r"(addr))

__global__ void __launch_bounds__(NTHR, 1)
gating_moe_kernel(const float* __restrict__ x,
                  const float* __restrict__ noise,
                  const float* __restrict__ W,
                  const float* __restrict__ b,
                  float* __restrict__ out)
{
    extern __shared__ float sm[];
    const uint32_t sb = smem_u32(sm);
    const int tid  = threadIdx.x;
    const int dp   = tid & 7;            // d-partition, lane bits 0..2
    const int tg   = (tid >> 3) & 15;    // token group (8 tokens)
    const int eg   = tid >> 7;           // expert group (8 experts)
    const int tok0 = blockIdx.x * BT;

    // ---- mbarrier init (full barriers only; recycling guarded by syncthreads) ----
    if (tid == 0) {
        MBARRIER_INIT(sb + MBAR_OFF + 0u, 1);
        MBARRIER_INIT(sb + MBAR_OFF + 8u, 1);
        MBARRIER_INIT(sb + MBAR_OFF + 16u, 1);
    }
    __syncthreads();

    // prefetch chunk c into stage s via TMA bulk copies (no LSU wavefronts)
    auto prefetch = [&](int c, int s) {
        const uint32_t mb = sb + MBAR_OFF + 8u * (uint32_t)s;
        const uint32_t xs = sb + (uint32_t)s * STAGE_B;
        if (tid == 0) MBARRIER_EXPECT_TX(mb, STAGE_B);
        if (tid < 128) {
            const char* g = (const char*)(x + (size_t)(tok0 + tid) * DIM + c * 64);
            BULK_CP256(xs + (uint32_t)tid * 256u, g, mb);
        } else if (tid < 144) {
            const int e = tid - 128;
            const char* g = (const char*)(W + (size_t)e * DIM + c * 64);
            BULK_CP256(xs + XSTAGE_B + (uint32_t)e * 256u, g, mb);
        }
    };

    // ---- accumulators: 8 tokens x 8 experts, packed f32x2 ----
    unsigned long long acc[8][8];
    #pragma unroll
    for (int t = 0; t < 8; t++)
        #pragma unroll
        for (int e = 0; e < 8; e++) acc[t][e] = 0ULL;

    prefetch(0, 0);
    prefetch(1, 1);

    for (int c = 0; c < NCHUNK; c++) {
        const int s  = c % 3;
        const int ph = (c / 3) & 1;
        MBARRIER_WAIT_PARITY(sb + MBAR_OFF + 8u * (uint32_t)s, ph);

        const uint32_t xs = sb + (uint32_t)s * STAGE_B;
        const uint32_t ws = xs + XSTAGE_B;

        #pragma unroll
        for (int j4 = 0; j4 < 2; j4++) {
            const uint32_t doff = (uint32_t)(dp * 16 + j4 * 128);
            unsigned long long xv[8][2];
            #pragma unroll
            for (int t = 0; t < 8; t++)
                LDSV2(xv[t][0], xv[t][1], xs + (uint32_t)((tg * 8 + t) * 256) + doff);
            #pragma unroll
            for (int e = 0; e < 8; e++) {
                unsigned long long w0, w1;
                LDSV2(w0, w1, ws + (uint32_t)((eg * 8 + e) * 256) + doff);
                #pragma unroll
                for (int t = 0; t < 8; t++) {
                    FMA2(acc[t][e], xv[t][0], w0);
                    FMA2(acc[t][e], xv[t][1], w1);
                }
            }
        }

        __syncthreads();                 // stage s fully consumed by all warps
        if (c + 2 < NCHUNK) prefetch(c + 2, (c + 2) % 3);
    }

    // ---- reduce: f32x2 halves + butterfly over dp (lane bits 0..2) ----
    const uint32_t lsb = sb + LS_OFF;
    #pragma unroll
    for (int t = 0; t < 8; t++) {
        #pragma unroll
        for (int e = 0; e < 8; e++) {
            float lo = __uint_as_float((unsigned)(acc[t][e] & 0xffffffffULL));
            float hi = __uint_as_float((unsigned)(acc[t][e] >> 32));
            float s = lo + hi;
            s += __shfl_xor_sync(~0u, s, 1);
            s += __shfl_xor_sync(~0u, s, 2);
            s += __shfl_xor_sync(~0u, s, 4);
            if (dp == 0)
                STS32(lsb + (uint32_t)(((tg * 8 + t) * 17 + (eg * 8 + e))) * 4u, s);
        }
    }
    __syncthreads();

    // ---- epilogue: bias + noise + top-2 + softmax + dense scatter ----
    if (tid < BT) {
        const int gtok = tok0 + tid;
        const float4* nz = (const float4*)(noise + (size_t)gtok * NE);
        float4 n0 = nz[0], n1 = nz[1], n2 = nz[2], n3 = nz[3];
        const float4* bb4 = (const float4*)b;
        float4 b0 = bb4[0], b1 = bb4[1], b2 = bb4[2], b3 = bb4[3];

        float nn[16] = {n0.x, n0.y, n0.z, n0.w, n1.x, n1.y, n1.z, n1.w,
                        n2.x, n2.y, n2.z, n2.w, n3.x, n3.y, n3.z, n3.w};
        float bv[16] = {b0.x, b0.y, b0.z, b0.w, b1.x, b1.y, b1.z, b1.w,
                        b2.x, b2.y, b2.z, b2.w, b3.x, b3.y, b3.z, b3.w};

        float v[16];
        #pragma unroll
        for (int e = 0; e < 16; e++) {
            float l;
            LDS32(l, lsb + (uint32_t)(tid * 17 + e) * 4u);
            v[e] = l + bv[e] + 0.1f * nn[e];
        }

        float v1 = -1e30f, v2 = -1e30f;
        int   i1 = -1,     i2 = -1;
        #pragma unroll
        for (int e = 0; e < 16; e++) {
            float val = v[e];
            if (val > v1)      { v2 = v1; i2 = i1; v1 = val; i1 = e; }
            else if (val > v2) { v2 = val; i2 = e; }
        }

        float ew  = expf(v2 - v1);
        float inv = 1.0f / (1.0f + ew);
        float w1  = inv;
        float w2  = ew * inv;

        float o[16];
        #pragma unroll
        for (int e = 0; e < 16; e++)
            o[e] = (e == i1) ? w1 : ((e == i2) ? w2 : 0.0f);

        float4* op = (float4*)(out + (size_t)gtok * NE);
        op[0] = make_float4(o[0],  o[1],  o[2],  o[3]);
        op[1] = make_float4(o[4],  o[5],  o[6],  o[7]);
        op[2] = make_float4(o[8],  o[9],  o[10], o[11]);
        op[3] = make_float4(o[12], o[13], o[14], o[15]);
    }
}

extern "C" void kernel_launch(void* const* d_in, const int* in_sizes, int n_in,
                              void* d_out, int out_size)
{
    const float* x     = (const float*)d_in[0];
    const float* noise = (const float*)d_in[1];
    const float* W     = (const float*)d_in[2];
    const float* b     = (const float*)d_in[3];
    float* out = (float*)d_out;

    cudaFuncSetAttribute(gating_moe_kernel,
                         cudaFuncAttributeMaxDynamicSharedMemorySize, SMEM_BYTES);
    gating_moe_kernel<<<TOK / BT, NTHR, SMEM_BYTES>>>(x, noise, W, b, out);
}

// round 5
// speedup vs baseline: 1.2886x; 1.2886x over previous
#include <cuda_runtime.h>
#include <cstdint>

#define TOK   16384
#define DIM   2048
#define NE    16
#define BT    128
#define NTHR  512
#define NCHUNK (DIM / 64)        // 32 chunks of 64 dims
#define NSTAGE 4

// stage = x[128 tok][64 f] (32768 B) + W[16 e][64 f] (4096 B)
#define XSTAGE_B  32768u
#define STAGE_B   36864u
#define LS_OFF    (4u * STAGE_B)              // logits [128][17] floats
#define SMEM_BYTES (4 * 36864 + 128 * 17 * 4) // 156160

__device__ __forceinline__ uint32_t smem_u32(const void* p) {
    uint32_t a;
    asm("{ .reg .u64 t; cvta.to.shared.u64 t, %1; cvt.u32.u64 %0, t; }" : "=r"(a) : "l"(p));
    return a;
}

#define CP_ASYNC16(saddr, gptr) \
    asm volatile("cp.async.cg.shared.global [%0], [%1], 16;" :: "r"(saddr), "l"(gptr))
#define CP_COMMIT() asm volatile("cp.async.commit_group;" ::: "memory")
#define CP_WAIT2()  asm volatile("cp.async.wait_group 2;" ::: "memory")
#define CP_WAIT1()  asm volatile("cp.async.wait_group 1;" ::: "memory")
#define CP_WAIT0()  asm volatile("cp.async.wait_group 0;" ::: "memory")

#define FMA2(c, a, b) asm("fma.rn.f32x2 %0, %1, %2, %0;" : "+l"(c) : "l"(a), "l"(b))
#define LDSV2(a, b, addr) \
    asm volatile("ld.shared.v2.b64 {%0, %1}, [%2];" : "=l"(a), "=l"(b) : "r"(addr))
#define STS32(addr, v) asm volatile("st.shared.f32 [%0], %1;" :: "r"(addr), "f"(v))
#define LDS32(v, addr) asm volatile("ld.shared.f32 %0, [%1];" : "=f"(v) : "r"(addr))

__global__ void __launch_bounds__(NTHR, 1)
gating_moe_kernel(const float* __restrict__ x,
                  const float* __restrict__ noise,
                  const float* __restrict__ W,
                  const float* __restrict__ b,
                  float* __restrict__ out)
{
    extern __shared__ float sm[];
    const uint32_t sb = smem_u32(sm);
    const int tid  = threadIdx.x;
    const int dp   = tid & 7;            // d-partition, lane bits 0..2
    const int tg   = (tid >> 3) & 31;    // token group (4 tokens), 4 groups/warp
    const int eg   = tid >> 8;           // expert group (8 experts), uniform per warp
    const int tok0 = blockIdx.x * BT;

    // prefetch chunk c into stage s: x 2048 f4 (4/thread) + W 256 f4 (threads 0..255)
    auto prefetch = [&](int c, int s) {
        const uint32_t base = sb + (uint32_t)s * STAGE_B;
        #pragma unroll
        for (int k = 0; k < 4; k++) {
            int idx = tid + NTHR * k;
            int t  = idx >> 4;
            int dv = idx & 15;
            const float* g = x + (size_t)(tok0 + t) * DIM + c * 64 + dv * 4;
            CP_ASYNC16(base + (uint32_t)(t * 256 + dv * 16), g);
        }
        if (tid < 256) {
            int e  = tid >> 4;
            int dv = tid & 15;
            const float* g = W + (size_t)e * DIM + c * 64 + dv * 4;
            CP_ASYNC16(base + XSTAGE_B + (uint32_t)(e * 256 + dv * 16), g);
        }
    };

    // accumulators: 4 tokens x 8 experts, packed f32x2
    unsigned long long acc[4][8];
    #pragma unroll
    for (int t = 0; t < 4; t++)
        #pragma unroll
        for (int e = 0; e < 8; e++) acc[t][e] = 0ULL;

    prefetch(0, 0); CP_COMMIT();
    prefetch(1, 1); CP_COMMIT();
    prefetch(2, 2); CP_COMMIT();

    for (int c = 0; c < NCHUNK; c++) {
        if (c < NCHUNK - 2)      { CP_WAIT2(); }
        else if (c == NCHUNK - 2){ CP_WAIT1(); }
        else                     { CP_WAIT0(); }
        __syncthreads();                       // chunk c visible; stage (c-1)%4 free
        if (c + 3 < NCHUNK) { prefetch(c + 3, (c + 3) & 3); CP_COMMIT(); }

        const uint32_t xs = sb + (uint32_t)(c & 3) * STAGE_B;
        const uint32_t ws = xs + XSTAGE_B;

        #pragma unroll
        for (int j4 = 0; j4 < 2; j4++) {
            const uint32_t doff = (uint32_t)(dp * 16 + j4 * 128);
            unsigned long long xv[4][2];
            #pragma unroll
            for (int t = 0; t < 4; t++)
                LDSV2(xv[t][0], xv[t][1], xs + (uint32_t)((tg * 4 + t) * 256) + doff);
            #pragma unroll
            for (int e = 0; e < 8; e++) {
                unsigned long long w0, w1;
                LDSV2(w0, w1, ws + (uint32_t)((eg * 8 + e) * 256) + doff);  // 1-wf broadcast
                #pragma unroll
                for (int t = 0; t < 4; t++) {
                    FMA2(acc[t][e], xv[t][0], w0);
                    FMA2(acc[t][e], xv[t][1], w1);
                }
            }
        }
    }
    __syncthreads();   // done reading pipeline smem before logits reuse

    // reduce: f32x2 halves + butterfly over dp (lane bits 0..2)
    const uint32_t lsb = sb + LS_OFF;
    #pragma unroll
    for (int t = 0; t < 4; t++) {
        #pragma unroll
        for (int e = 0; e < 8; e++) {
            float lo = __uint_as_float((unsigned)(acc[t][e] & 0xffffffffULL));
            float hi = __uint_as_float((unsigned)(acc[t][e] >> 32));
            float s = lo + hi;
            s += __shfl_xor_sync(~0u, s, 1);
            s += __shfl_xor_sync(~0u, s, 2);
            s += __shfl_xor_sync(~0u, s, 4);
            if (dp == 0)
                STS32(lsb + (uint32_t)(((tg * 4 + t) * 17 + (eg * 8 + e))) * 4u, s);
        }
    }
    __syncthreads();

    // epilogue: bias + noise + top-2 + softmax + dense scatter
    if (tid < BT) {
        const int gtok = tok0 + tid;
        const float4* nz = (const float4*)(noise + (size_t)gtok * NE);
        float4 n0 = nz[0], n1 = nz[1], n2 = nz[2], n3 = nz[3];
        const float4* bb4 = (const float4*)b;
        float4 b0 = bb4[0], b1 = bb4[1], b2 = bb4[2], b3 = bb4[3];

        float nn[16] = {n0.x, n0.y, n0.z, n0.w, n1.x, n1.y, n1.z, n1.w,
                        n2.x, n2.y, n2.z, n2.w, n3.x, n3.y, n3.z, n3.w};
        float bv[16] = {b0.x, b0.y, b0.z, b0.w, b1.x, b1.y, b1.z, b1.w,
                        b2.x, b2.y, b2.z, b2.w, b3.x, b3.y, b3.z, b3.w};

        float v[16];
        #pragma unroll
        for (int e = 0; e < 16; e++) {
            float l;
            LDS32(l, lsb + (uint32_t)(tid * 17 + e) * 4u);
            v[e] = l + bv[e] + 0.1f * nn[e];
        }

        float v1 = -1e30f, v2 = -1e30f;
        int   i1 = -1,     i2 = -1;
        #pragma unroll
        for (int e = 0; e < 16; e++) {
            float val = v[e];
            if (val > v1)      { v2 = v1; i2 = i1; v1 = val; i1 = e; }
            else if (val > v2) { v2 = val; i2 = e; }
        }

        float ew  = expf(v2 - v1);
        float inv = 1.0f / (1.0f + ew);
        float w1  = inv;
        float w2  = ew * inv;

        float o[16];
        #pragma unroll
        for (int e = 0; e < 16; e++)
            o[e] = (e == i1) ? w1 : ((e == i2) ? w2 : 0.0f);

        float4* op = (float4*)(out + (size_t)gtok * NE);
        op[0] = make_float4(o[0],  o[1],  o[2],  o[3]);
        op[1] = make_float4(o[4],  o[5],  o[6],  o[7]);
        op[2] = make_float4(o[8],  o[9],  o[10], o[11]);
        op[3] = make_float4(o[12], o[13], o[14], o[15]);
    }
}

extern "C" void kernel_launch(void* const* d_in, const int* in_sizes, int n_in,
                              void* d_out, int out_size)
{
    const float* x     = (const float*)d_in[0];
    const float* noise = (const float*)d_in[1];
    const float* W     = (const float*)d_in[2];
    const float* b     = (const float*)d_in[3];
    float* out = (float*)d_out;

    cudaFuncSetAttribute(gating_moe_kernel,
                         cudaFuncAttributeMaxDynamicSharedMemorySize, SMEM_BYTES);
    gating_moe_kernel<<<TOK / BT, NTHR, SMEM_BYTES>>>(x, noise, W, b, out);
}